// round 1
// baseline (speedup 1.0000x reference)
#include <cuda_runtime.h>
#include <cstdint>

#define NTOK 16384
#define DIN 64
#define DOUT 64
#define NC 512
#define KSEL 16
#define NASSIGN (NTOK*KSEL)

typedef unsigned long long u64;

// ---------------- scratch (device globals: no allocation allowed) -------------
__device__ float g_dist[NTOK*NC];       // 32 MB biased distance keys
__device__ float g_scores[NASSIGN];     // softmax scores per (token, j)
__device__ int   g_idx[NASSIGN];        // selected center per (token, j)
__device__ int   g_cnt[NC];
__device__ int   g_off[NC];
__device__ int   g_cursor[NC];
__device__ int   g_tok[NASSIGN];        // bucket -> token id
__device__ float g_ascore[NASSIGN];     // bucket -> score
__device__ int   g_slot[NASSIGN];       // (token,j) -> bucket position
__device__ float g_part[(size_t)NASSIGN*DOUT]; // 67 MB partial outputs
__device__ float g_c2[NC];              // ||c||^2 + 1024 bias
__device__ int   g_tiles[8192];         // (center, rowStart) pairs
__device__ int   g_ntiles;

// ---------------- packed f32x2 helpers ----------------------------------------
__device__ __forceinline__ u64 dupf(float x){
    u64 r; asm("mov.b64 %0, {%1, %1};" : "=l"(r) : "f"(x)); return r;
}
__device__ __forceinline__ void ffma2(u64 &d, u64 a, u64 b){
    asm("fma.rn.f32x2 %0, %1, %2, %0;" : "+l"(d) : "l"(a), "l"(b));
}
__device__ __forceinline__ u64 ffma2v(u64 a, u64 b, u64 c){
    u64 d; asm("fma.rn.f32x2 %0, %1, %2, %3;" : "=l"(d) : "l"(a), "l"(b), "l"(c)); return d;
}
__device__ __forceinline__ u64 fadd2(u64 a, u64 b){
    u64 r; asm("add.rn.f32x2 %0, %1, %2;" : "=l"(r) : "l"(a), "l"(b)); return r;
}
__device__ __forceinline__ u64 fmul2(u64 a, u64 b){
    u64 r; asm("mul.rn.f32x2 %0, %1, %2;" : "=l"(r) : "l"(a), "l"(b)); return r;
}

// ---------------- K0: c2 (+bias) and zero counts -------------------------------
__global__ void k_prep(const float* __restrict__ ctrs){
    int c = blockIdx.x*32 + threadIdx.x;   // 512 threads over 16 blocks
    g_cnt[c] = 0;
    const float4* c4 = (const float4*)ctrs;
    float s = 1024.0f;  // bias keeps keys > 0 (|2 x.c| << 1024); cancels in softmax
    #pragma unroll
    for(int seg=0; seg<16; seg++){
        float4 v = c4[c*16 + seg];
        s += v.x*v.x + v.y*v.y + v.z*v.z + v.w*v.w;
    }
    g_c2[c] = s;
}

// ---------------- K1a: distance-key GEMM  key = c2b - 2*(x.c) ------------------
// tile: 128 tokens x 64 centers, K=64.  block 128 thr, thread = 8 tok x 8 ctr.
__global__ __launch_bounds__(128) void k_dist(const float* __restrict__ x,
                                              const float* __restrict__ ctrs){
    __shared__ float cs[DIN*64];    // cs[k*64 + cLocal]  (transposed)
    __shared__ float xs[DIN*128];   // xs[k*128 + tLocal] (transposed)
    int ctile = blockIdx.x*64;
    int ttile = blockIdx.y*128;
    int tid = threadIdx.x;

    const float4* c4 = (const float4*)ctrs;
    #pragma unroll
    for(int it=0; it<8; it++){
        int idx2 = tid + 128*it;
        int rr = idx2 >> 4, seg = idx2 & 15;
        float4 v = c4[(ctile+rr)*16 + seg];
        int b = seg*4;
        cs[(b+0)*64+rr]=v.x; cs[(b+1)*64+rr]=v.y; cs[(b+2)*64+rr]=v.z; cs[(b+3)*64+rr]=v.w;
    }
    const float4* x4 = (const float4*)x;
    #pragma unroll
    for(int it=0; it<16; it++){
        int idx2 = tid + 128*it;
        int rr = idx2 >> 4, seg = idx2 & 15;
        float4 v = x4[(ttile+rr)*16 + seg];
        int b = seg*4;
        xs[(b+0)*128+rr]=v.x; xs[(b+1)*128+rr]=v.y; xs[(b+2)*128+rr]=v.z; xs[(b+3)*128+rr]=v.w;
    }
    __syncthreads();

    int og = tid & 7, tg = tid >> 3;
    int c0 = og*8, r0 = tg*8;
    u64 acc[8][4];
    #pragma unroll
    for(int i=0;i<8;i++){ acc[i][0]=0; acc[i][1]=0; acc[i][2]=0; acc[i][3]=0; }

    #pragma unroll 8
    for(int k=0;k<64;k++){
        const u64* wp = (const u64*)&cs[k*64 + c0];
        u64 w0=wp[0], w1=wp[1], w2=wp[2], w3=wp[3];
        #pragma unroll
        for(int i=0;i<8;i++){
            u64 xv = dupf(xs[k*128 + r0 + i]);
            ffma2(acc[i][0], xv, w0);
            ffma2(acc[i][1], xv, w1);
            ffma2(acc[i][2], xv, w2);
            ffma2(acc[i][3], xv, w3);
        }
    }
    const u64* c2p = (const u64*)&g_c2[ctile + c0];
    u64 cw0=c2p[0], cw1=c2p[1], cw2=c2p[2], cw3=c2p[3];
    u64 m2 = dupf(-2.0f);
    #pragma unroll
    for(int i=0;i<8;i++){
        u64 o0v = ffma2v(acc[i][0], m2, cw0);
        u64 o1v = ffma2v(acc[i][1], m2, cw1);
        u64 o2v = ffma2v(acc[i][2], m2, cw2);
        u64 o3v = ffma2v(acc[i][3], m2, cw3);
        u64* dst = (u64*)&g_dist[(size_t)(ttile + r0 + i)*NC + ctile + c0];
        dst[0]=o0v; dst[1]=o1v; dst[2]=o2v; dst[3]=o3v;
    }
}

// ---------------- K1b: per-token top-16 (smallest keys) + softmax + counts -----
__global__ __launch_bounds__(256) void k_topk(){
    int warp = blockIdx.x*8 + (threadIdx.x >> 5);   // token id
    int lane = threadIdx.x & 31;
    int wl   = threadIdx.x >> 5;
    __shared__ float sd[8][16];
    __shared__ int   sci[8][16];

    const float* row = g_dist + (size_t)warp*NC;
    float v[16];
    #pragma unroll
    for(int i=0;i<16;i++) v[i] = row[lane + 32*i];
    float lmin = v[0]; int larg = 0;
    #pragma unroll
    for(int i=1;i<16;i++){ if(v[i] < lmin){ lmin=v[i]; larg=i; } }

    #pragma unroll 1
    for(int j=0;j<16;j++){
        // keys are > 0 so float bits are order-preserving as unsigned
        unsigned mb   = __reduce_min_sync(0xffffffffu, __float_as_uint(lmin));
        unsigned ball = __ballot_sync(0xffffffffu, __float_as_uint(lmin) == mb);
        int wlan = __ffs(ball) - 1;
        if(lane == wlan){
            sd[wl][j]  = lmin;
            sci[wl][j] = larg*32 + lane;
            v[larg] = 3.0e38f;
            lmin = v[0]; larg = 0;
            #pragma unroll
            for(int i=1;i<16;i++){ if(v[i] < lmin){ lmin=v[i]; larg=i; } }
        }
        __syncwarp();
    }
    if(lane < 16){
        float d = sd[wl][lane];
        float m = sd[wl][0];             // smallest key = largest neg-dist
        float e = expf(m - d);
        float s = e;
        #pragma unroll
        for(int o=8;o>=1;o>>=1) s += __shfl_xor_sync(0x0000ffffu, s, o);
        float sc = e / s;
        int c = sci[wl][lane];
        g_scores[warp*16 + lane] = sc;
        g_idx[warp*16 + lane]    = c;
        atomicAdd(&g_cnt[c], 1);
    }
}

// ---------------- K2: prefix sums + tile descriptor build ----------------------
__global__ __launch_bounds__(512) void k_scan(){
    __shared__ int sb[512];
    int c = threadIdx.x;
    int cn = g_cnt[c];
    sb[c] = cn; __syncthreads();
    for(int off=1; off<512; off<<=1){
        int v = (c >= off) ? sb[c-off] : 0;
        __syncthreads();
        sb[c] += v;
        __syncthreads();
    }
    int offc = sb[c] - cn;
    g_off[c] = offc;
    g_cursor[c] = offc;
    int t = (cn + 127) >> 7;
    __syncthreads();
    sb[c] = t; __syncthreads();
    for(int off=1; off<512; off<<=1){
        int v = (c >= off) ? sb[c-off] : 0;
        __syncthreads();
        sb[c] += v;
        __syncthreads();
    }
    int tb = sb[c] - t;
    for(int i=0;i<t;i++){
        g_tiles[2*(tb+i)]   = c;
        g_tiles[2*(tb+i)+1] = i << 7;
    }
    if(c == 511) g_ntiles = sb[c];
}

// ---------------- K3: scatter assignments into center buckets ------------------
__global__ void k_scatter(){
    int tid = blockIdx.x*blockDim.x + threadIdx.x;   // (token<<4)|j
    int c = g_idx[tid];
    float s = g_scores[tid];
    int pos = atomicAdd(&g_cursor[c], 1);
    g_tok[pos] = tid >> 4;
    g_ascore[pos] = s;
    g_slot[tid] = pos;
}

// ---------------- K4: grouped GEMM per (center, 128-row tile) ------------------
// part[row] = score * (x[token] @ Wv[c] + Ov[c]).  block 128 thr, thread = 8x8.
__global__ __launch_bounds__(128,4) void k_gemm(const float* __restrict__ x,
                                                const float* __restrict__ Wv,
                                                const float* __restrict__ Ov){
    __shared__ float ws[DIN*DOUT];   // ws[k*64 + p]   (row-major, 16 KB)
    __shared__ float xs[DIN*128];    // xs[k*128 + i]  (transposed, 32 KB)
    int nt = g_ntiles;
    int tid = threadIdx.x;
    int og = tid & 7, tg = tid >> 3;
    int o0 = og*8, r0 = tg*8;

    for(int tile = blockIdx.x; tile < nt; tile += gridDim.x){
        int c      = g_tiles[2*tile];
        int rstart = g_tiles[2*tile+1];
        int base   = g_off[c] + rstart;
        int m      = g_cnt[c] - rstart; if(m > 128) m = 128;
        __syncthreads();   // previous tile's smem reads done before overwrite

        const float4* wv4 = (const float4*)(Wv + (size_t)c*4096);
        float4* ws4 = (float4*)ws;
        #pragma unroll
        for(int i=0;i<8;i++) ws4[tid + 128*i] = wv4[tid + 128*i];

        const float4* x4 = (const float4*)x;
        #pragma unroll
        for(int it=0; it<16; it++){
            int idx2 = tid + 128*it;
            int rr = idx2 >> 4, seg = idx2 & 15;
            if(rr < m){
                float4 v = x4[g_tok[base+rr]*16 + seg];
                int b = seg*4;
                xs[(b+0)*128+rr]=v.x; xs[(b+1)*128+rr]=v.y;
                xs[(b+2)*128+rr]=v.z; xs[(b+3)*128+rr]=v.w;
            }
        }
        __syncthreads();

        u64 acc[8][4];
        #pragma unroll
        for(int i=0;i<8;i++){ acc[i][0]=0; acc[i][1]=0; acc[i][2]=0; acc[i][3]=0; }

        #pragma unroll 8
        for(int k=0;k<64;k++){
            const u64* wp = (const u64*)&ws[k*64 + o0];
            u64 w0=wp[0], w1=wp[1], w2=wp[2], w3=wp[3];
            #pragma unroll
            for(int i=0;i<8;i++){
                u64 xv = dupf(xs[k*128 + r0 + i]);
                ffma2(acc[i][0], xv, w0);
                ffma2(acc[i][1], xv, w1);
                ffma2(acc[i][2], xv, w2);
                ffma2(acc[i][3], xv, w3);
            }
        }
        const u64* ovp = (const u64*)(Ov + (size_t)c*64 + o0);
        u64 ov0=ovp[0], ov1=ovp[1], ov2=ovp[2], ov3=ovp[3];
        #pragma unroll
        for(int i=0;i<8;i++){
            int r = r0 + i;
            if(r < m){
                u64 sv = dupf(g_ascore[base + r]);
                u64 q0 = fmul2(fadd2(acc[i][0], ov0), sv);
                u64 q1 = fmul2(fadd2(acc[i][1], ov1), sv);
                u64 q2 = fmul2(fadd2(acc[i][2], ov2), sv);
                u64 q3 = fmul2(fadd2(acc[i][3], ov3), sv);
                u64* dst = (u64*)&g_part[(size_t)(base + r)*64 + o0];
                dst[0]=q0; dst[1]=q1; dst[2]=q2; dst[3]=q3;
            }
        }
    }
}

// ---------------- K5: gather-reduce the 16 partials per token ------------------
__global__ __launch_bounds__(256) void k_reduce(float* __restrict__ out){
    int t   = blockIdx.x*4 + (threadIdx.x >> 6);
    int col = threadIdx.x & 63;
    const int* sl = &g_slot[t*16];
    float acc = 0.0f;
    #pragma unroll
    for(int j=0;j<16;j++){
        acc += g_part[(size_t)sl[j]*64 + col];
    }
    out[t*64 + col] = acc;
}

// ---------------- launch -------------------------------------------------------
extern "C" void kernel_launch(void* const* d_in, const int* in_sizes, int n_in,
                              void* d_out, int out_size){
    const float* x    = (const float*)d_in[0];
    const float* ctrs = (const float*)d_in[1];
    const float* Wv   = (const float*)d_in[2];
    const float* Ov   = (const float*)d_in[3];
    float* out = (float*)d_out;

    k_prep   <<<16, 32>>>(ctrs);
    k_dist   <<<dim3(8,128), 128>>>(x, ctrs);
    k_topk   <<<2048, 256>>>();
    k_scan   <<<1, 512>>>();
    k_scatter<<<512, 512>>>();
    k_gemm   <<<592, 128>>>(x, Wv, Ov);
    k_reduce <<<4096, 256>>>(out);
}

// round 2
// speedup vs baseline: 1.1077x; 1.1077x over previous
#include <cuda_runtime.h>
#include <cstdint>

#define NTOK 16384
#define DIN 64
#define DOUT 64
#define NC 512
#define KSEL 16
#define NASSIGN (NTOK*KSEL)

typedef unsigned long long u64;

// ---------------- scratch (device globals: no allocation allowed) -------------
__device__ float g_dist[NTOK*NC];       // 32 MB biased distance keys [tok][c]
__device__ float g_ctrT[DIN*NC];        // centers transposed [k][c]
__device__ float g_scores[NASSIGN];     // softmax scores per (token, j)
__device__ int   g_idx[NASSIGN];        // selected center per (token, j)
__device__ int   g_cnt[NC];
__device__ int   g_off[NC];
__device__ int   g_cursor[NC];
__device__ int   g_tok[NASSIGN];        // bucket -> token id
__device__ float g_ascore[NASSIGN];     // bucket -> score
__device__ int   g_dslot[NASSIGN];      // bucket -> (token*16+j) destination slot
__device__ float g_part[(size_t)NASSIGN*DOUT]; // 67 MB partials, slot-addressed
__device__ float g_c2[NC];              // ||c||^2 + 1024 bias
__device__ int   g_tiles[8192];         // (center, rowStart) pairs
__device__ int   g_ntiles;
__device__ int   g_work;                // dynamic tile cursor for k_gemm

// ---------------- packed f32x2 helpers ----------------------------------------
__device__ __forceinline__ u64 dupf(float x){
    u64 r; asm("mov.b64 %0, {%1, %1};" : "=l"(r) : "f"(x)); return r;
}
__device__ __forceinline__ u64 pk(float a, float b){
    u64 r; asm("mov.b64 %0, {%1, %2};" : "=l"(r) : "f"(a), "f"(b)); return r;
}
__device__ __forceinline__ void ffma2(u64 &d, u64 a, u64 b){
    asm("fma.rn.f32x2 %0, %1, %2, %0;" : "+l"(d) : "l"(a), "l"(b));
}
__device__ __forceinline__ u64 ffma2v(u64 a, u64 b, u64 c){
    u64 d; asm("fma.rn.f32x2 %0, %1, %2, %3;" : "=l"(d) : "l"(a), "l"(b), "l"(c)); return d;
}
__device__ __forceinline__ u64 fadd2(u64 a, u64 b){
    u64 r; asm("add.rn.f32x2 %0, %1, %2;" : "=l"(r) : "l"(a), "l"(b)); return r;
}
__device__ __forceinline__ u64 fmul2(u64 a, u64 b){
    u64 r; asm("mul.rn.f32x2 %0, %1, %2;" : "=l"(r) : "l"(a), "l"(b)); return r;
}

// ---------------- K0: transpose centers, c2 (+bias), zero counters -------------
__global__ void k_prep(const float* __restrict__ ctrs){
    int bid = blockIdx.x, tid = threadIdx.x;
    if(bid < 128){
        int e = bid*256 + tid;           // 32768 elements
        int k = e >> 9, c = e & 511;
        g_ctrT[k*NC + c] = ctrs[c*DIN + k];
    } else {
        int c = (bid-128)*256 + tid;     // 512 centers over 2 blocks
        g_cnt[c] = 0;
        if(c == 0) g_work = 0;
        const float4* c4 = (const float4*)ctrs;
        float s = 1024.0f;  // bias keeps keys > 0; cancels in softmax
        #pragma unroll
        for(int seg=0; seg<16; seg++){
            float4 v = c4[c*16 + seg];
            s += v.x*v.x + v.y*v.y + v.z*v.z + v.w*v.w;
        }
        g_c2[c] = s;
    }
}

// ---------------- K1a: distance-key GEMM  key = c2b - 2*(x.c) ------------------
// block: 128 tokens x (2 x 64 centers).  128 thr, thread = 8 tok x 8 ctr.
// xs stored with XOR swizzle col^=8*(r&3): conflict-free stores AND loads.
__global__ __launch_bounds__(128) void k_dist(const float* __restrict__ x){
    __shared__ float cs[DIN*64];     // cs[k*64 + c]  (k-major, from g_ctrT)
    __shared__ float xs[128*DIN];    // xs[r*64 + (k ^ 8*(r&3))]
    int tid = threadIdx.x;
    int ttile = blockIdx.y*128;

    const float4* x4 = (const float4*)x;
    #pragma unroll
    for(int it=0; it<16; it++){
        int idx2 = tid + 128*it;
        int rr = idx2 >> 4, seg = idx2 & 15;
        float4 v = x4[(ttile+rr)*16 + seg];
        *(float4*)&xs[rr*64 + ((seg*4) ^ ((rr&3)*8))] = v;
    }

    int og = tid & 7, tg = tid >> 3;        // og 0..7, tg 0..15
    int xsw = (tg & 3) * 8;                 // per-thread constant swizzle

    for(int ct=0; ct<2; ct++){
        int ctile = blockIdx.x*128 + ct*64;
        if(ct) __syncthreads();
        #pragma unroll
        for(int f=0; f<8; f++){             // copy 64x64 center slab, k-major
            int e = tid + 128*f;
            int row = e >> 4, q = e & 15;
            *(float4*)&cs[row*64 + q*4] =
                *(const float4*)&g_ctrT[row*NC + ctile + q*4];
        }
        __syncthreads();

        u64 acc[8][4];
        #pragma unroll
        for(int i=0;i<8;i++){ acc[i][0]=0; acc[i][1]=0; acc[i][2]=0; acc[i][3]=0; }

        #pragma unroll 8
        for(int k=0;k<64;k++){
            float4 wa = *(const float4*)&cs[k*64 + og*8];
            float4 wb = *(const float4*)&cs[k*64 + og*8 + 4];
            u64 w0=pk(wa.x,wa.y), w1=pk(wa.z,wa.w), w2=pk(wb.x,wb.y), w3=pk(wb.z,wb.w);
            int kx = k ^ xsw;
            #pragma unroll
            for(int i=0;i<8;i++){
                u64 xv = dupf(xs[(tg + 16*i)*64 + kx]);
                ffma2(acc[i][0], xv, w0);
                ffma2(acc[i][1], xv, w1);
                ffma2(acc[i][2], xv, w2);
                ffma2(acc[i][3], xv, w3);
            }
        }
        const u64* c2p = (const u64*)&g_c2[ctile + og*8];
        u64 cw0=c2p[0], cw1=c2p[1], cw2=c2p[2], cw3=c2p[3];
        u64 m2 = dupf(-2.0f);
        #pragma unroll
        for(int i=0;i<8;i++){
            int r = tg + 16*i;
            u64* dst = (u64*)&g_dist[(size_t)(ttile + r)*NC + ctile + og*8];
            dst[0] = ffma2v(acc[i][0], m2, cw0);
            dst[1] = ffma2v(acc[i][1], m2, cw1);
            dst[2] = ffma2v(acc[i][2], m2, cw2);
            dst[3] = ffma2v(acc[i][3], m2, cw3);
        }
    }
}

// ---------------- K1b: per-token top-16 (smallest keys) + softmax + counts -----
__global__ __launch_bounds__(256) void k_topk(){
    int warp = blockIdx.x*8 + (threadIdx.x >> 5);   // token id
    int lane = threadIdx.x & 31;
    int wl   = threadIdx.x >> 5;
    __shared__ float sd[8][16];
    __shared__ int   sci[8][16];

    const float4* r4 = (const float4*)(g_dist + (size_t)warp*NC + lane*16);
    float v[16];
    float4 a0=r4[0], a1=r4[1], a2=r4[2], a3=r4[3];
    v[0]=a0.x; v[1]=a0.y; v[2]=a0.z; v[3]=a0.w;
    v[4]=a1.x; v[5]=a1.y; v[6]=a1.z; v[7]=a1.w;
    v[8]=a2.x; v[9]=a2.y; v[10]=a2.z; v[11]=a2.w;
    v[12]=a3.x; v[13]=a3.y; v[14]=a3.z; v[15]=a3.w;

    float lmin = v[0]; int larg = 0;
    #pragma unroll
    for(int i=1;i<16;i++){ if(v[i] < lmin){ lmin=v[i]; larg=i; } }

    #pragma unroll 1
    for(int j=0;j<16;j++){
        // keys are > 0 so float bits are order-preserving as unsigned
        unsigned mb   = __reduce_min_sync(0xffffffffu, __float_as_uint(lmin));
        unsigned ball = __ballot_sync(0xffffffffu, __float_as_uint(lmin) == mb);
        int wlan = __ffs(ball) - 1;
        if(lane == wlan){
            sd[wl][j]  = lmin;
            sci[wl][j] = lane*16 + larg;
            v[larg] = 3.0e38f;
            lmin = v[0]; larg = 0;
            #pragma unroll
            for(int i=1;i<16;i++){ if(v[i] < lmin){ lmin=v[i]; larg=i; } }
        }
        __syncwarp();
    }
    if(lane < 16){
        float d = sd[wl][lane];
        float m = sd[wl][0];             // smallest key = largest neg-dist
        float e = expf(m - d);
        float s = e;
        #pragma unroll
        for(int o=8;o>=1;o>>=1) s += __shfl_xor_sync(0x0000ffffu, s, o);
        float sc = e / s;
        int c = sci[wl][lane];
        g_scores[warp*16 + lane] = sc;
        g_idx[warp*16 + lane]    = c;
        atomicAdd(&g_cnt[c], 1);
    }
}

// ---------------- K2: prefix sums + tile descriptor build (shuffle scan) -------
__global__ __launch_bounds__(512) void k_scan(){
    __shared__ int wsum[16];
    int c = threadIdx.x, lane = c & 31, w = c >> 5;
    int cn = g_cnt[c];

    int s = cn;
    #pragma unroll
    for(int o=1;o<32;o<<=1){ int v=__shfl_up_sync(0xffffffffu,s,o); if(lane>=o) s+=v; }
    if(lane==31) wsum[w] = s;
    __syncthreads();
    if(w==0){
        int t = (lane<16) ? wsum[lane] : 0;
        #pragma unroll
        for(int o=1;o<16;o<<=1){ int v=__shfl_up_sync(0xffffffffu,t,o); if(lane>=o) t+=v; }
        if(lane<16) wsum[lane] = t;
    }
    __syncthreads();
    int inc = s + ((w>0) ? wsum[w-1] : 0);
    int off = inc - cn;
    g_off[c] = off;
    g_cursor[c] = off;

    int t = (cn + 127) >> 7;
    __syncthreads();
    int s2 = t;
    #pragma unroll
    for(int o=1;o<32;o<<=1){ int v=__shfl_up_sync(0xffffffffu,s2,o); if(lane>=o) s2+=v; }
    if(lane==31) wsum[w] = s2;
    __syncthreads();
    if(w==0){
        int tt = (lane<16) ? wsum[lane] : 0;
        #pragma unroll
        for(int o=1;o<16;o<<=1){ int v=__shfl_up_sync(0xffffffffu,tt,o); if(lane>=o) tt+=v; }
        if(lane<16) wsum[lane] = tt;
    }
    __syncthreads();
    int tinc = s2 + ((w>0) ? wsum[w-1] : 0);
    int tb = tinc - t;
    for(int i=0;i<t;i++){
        g_tiles[2*(tb+i)]   = c;
        g_tiles[2*(tb+i)+1] = i << 7;
    }
    if(c == 511) g_ntiles = tinc;
}

// ---------------- K3: scatter assignments into center buckets ------------------
__global__ void k_scatter(){
    int tid = blockIdx.x*blockDim.x + threadIdx.x;   // (token<<4)|j
    int c = g_idx[tid];
    float s = g_scores[tid];
    int pos = atomicAdd(&g_cursor[c], 1);
    g_tok[pos]   = tid >> 4;
    g_ascore[pos]= s;
    g_dslot[pos] = tid;            // where this partial's result must land
}

// ---------------- K4: grouped GEMM per (center, 128-row tile) ------------------
// part[slot] = score * (x[token] @ Wv[c] + Ov[c]).  Dynamic tile scheduling.
__global__ __launch_bounds__(128) void k_gemm(const float* __restrict__ x,
                                              const float* __restrict__ Wv,
                                              const float* __restrict__ Ov){
    __shared__ float ws[DIN*DOUT];   // ws[k*64 + p] (row-major copy of Wv[c])
    __shared__ float xs[128*DIN];    // swizzled like k_dist
    __shared__ int s_tile;
    int nt = g_ntiles;
    int tid = threadIdx.x;
    int og = tid & 7, tg = tid >> 3;
    int xsw = (tg & 3) * 8;
    const float4* x4 = (const float4*)x;

    while(true){
        __syncthreads();             // smem reuse + s_tile protection
        if(tid == 0) s_tile = atomicAdd(&g_work, 1);
        __syncthreads();
        int tile = s_tile;
        if(tile >= nt) break;

        int c      = g_tiles[2*tile];
        int rstart = g_tiles[2*tile+1];
        int base   = g_off[c] + rstart;
        int m      = g_cnt[c] - rstart; if(m > 128) m = 128;

        const float4* wv4 = (const float4*)(Wv + (size_t)c*4096);
        float4* ws4 = (float4*)ws;
        #pragma unroll
        for(int f=0; f<8; f++) ws4[tid + 128*f] = wv4[tid + 128*f];

        #pragma unroll
        for(int it=0; it<16; it++){
            int idx2 = tid + 128*it;
            int rr = idx2 >> 4, seg = idx2 & 15;
            if(rr < m){
                float4 v = x4[g_tok[base+rr]*16 + seg];
                *(float4*)&xs[rr*64 + ((seg*4) ^ ((rr&3)*8))] = v;
            }
        }
        __syncthreads();

        u64 acc[8][4];
        #pragma unroll
        for(int i=0;i<8;i++){ acc[i][0]=0; acc[i][1]=0; acc[i][2]=0; acc[i][3]=0; }

        #pragma unroll 8
        for(int k=0;k<64;k++){
            float4 wa = *(const float4*)&ws[k*64 + og*8];
            float4 wb = *(const float4*)&ws[k*64 + og*8 + 4];
            u64 w0=pk(wa.x,wa.y), w1=pk(wa.z,wa.w), w2=pk(wb.x,wb.y), w3=pk(wb.z,wb.w);
            int kx = k ^ xsw;
            #pragma unroll
            for(int i=0;i<8;i++){
                u64 xv = dupf(xs[(tg + 16*i)*64 + kx]);
                ffma2(acc[i][0], xv, w0);
                ffma2(acc[i][1], xv, w1);
                ffma2(acc[i][2], xv, w2);
                ffma2(acc[i][3], xv, w3);
            }
        }
        const u64* ovp = (const u64*)(Ov + (size_t)c*64 + og*8);
        u64 ov0=ovp[0], ov1=ovp[1], ov2=ovp[2], ov3=ovp[3];
        #pragma unroll
        for(int i=0;i<8;i++){
            int r = tg + 16*i;
            if(r < m){
                int slot = g_dslot[base + r];
                u64 sv = dupf(g_ascore[base + r]);
                u64* dst = (u64*)&g_part[(size_t)slot*64 + og*8];
                dst[0] = fmul2(fadd2(acc[i][0], ov0), sv);
                dst[1] = fmul2(fadd2(acc[i][1], ov1), sv);
                dst[2] = fmul2(fadd2(acc[i][2], ov2), sv);
                dst[3] = fmul2(fadd2(acc[i][3], ov3), sv);
            }
        }
    }
}

// ---------------- K5: streamed reduce of 16 contiguous partials per token ------
__global__ __launch_bounds__(256) void k_reduce(float* __restrict__ out){
    int t  = blockIdx.x*16 + (threadIdx.x >> 4);
    int c4 = threadIdx.x & 15;
    const float4* p = (const float4*)(g_part + (size_t)t*16*64) + c4;
    float4 acc = make_float4(0.f,0.f,0.f,0.f);
    #pragma unroll
    for(int j=0;j<16;j++){
        float4 v = p[j*16];
        acc.x += v.x; acc.y += v.y; acc.z += v.z; acc.w += v.w;
    }
    ((float4*)out)[t*16 + c4] = acc;
}

// ---------------- launch -------------------------------------------------------
extern "C" void kernel_launch(void* const* d_in, const int* in_sizes, int n_in,
                              void* d_out, int out_size){
    const float* x    = (const float*)d_in[0];
    const float* ctrs = (const float*)d_in[1];
    const float* Wv   = (const float*)d_in[2];
    const float* Ov   = (const float*)d_in[3];
    float* out = (float*)d_out;

    k_prep   <<<130, 256>>>(ctrs);
    k_dist   <<<dim3(4,128), 128>>>(x);
    k_topk   <<<2048, 256>>>();
    k_scan   <<<1, 512>>>();
    k_scatter<<<512, 512>>>();
    k_gemm   <<<592, 128>>>(x, Wv, Ov);
    k_reduce <<<1024, 256>>>(out);
}

// round 3
// speedup vs baseline: 1.1092x; 1.0013x over previous
#include <cuda_runtime.h>
#include <cstdint>

#define NTOK 16384
#define DIN 64
#define DOUT 64
#define NC 512
#define KSEL 16
#define NASSIGN (NTOK*KSEL)

typedef unsigned long long u64;

// ---------------- scratch (device globals: no allocation allowed) -------------
__device__ float g_ctrT[DIN*NC];        // centers transposed [k][c]
__device__ float g_scores[NASSIGN];     // softmax scores per (token, j)
__device__ int   g_idx[NASSIGN];        // selected center per (token, j)
__device__ int   g_cnt[NC];
__device__ int   g_off[NC];
__device__ int   g_cursor[NC];
__device__ int   g_tok[NASSIGN];        // bucket -> token id
__device__ float g_ascore[NASSIGN];     // bucket -> score
__device__ int   g_dslot[NASSIGN];      // bucket -> (token*16+j) destination slot
__device__ float g_part[(size_t)NASSIGN*DOUT]; // 67 MB partials, slot-addressed
__device__ float g_c2[NC];              // ||c||^2 + 1024 bias
__device__ int   g_tiles[8192];         // (center, rowStart) pairs
__device__ int   g_ntiles;
__device__ int   g_work;                // dynamic tile cursor for k_gemm
__device__ int   g_flag;                // scan-done flag for k_ss

// ---------------- packed f32x2 helpers ----------------------------------------
__device__ __forceinline__ u64 dupf(float x){
    u64 r; asm("mov.b64 %0, {%1, %1};" : "=l"(r) : "f"(x)); return r;
}
__device__ __forceinline__ void ffma2(u64 &d, u64 a, u64 b){
    asm("fma.rn.f32x2 %0, %1, %2, %0;" : "+l"(d) : "l"(a), "l"(b));
}
__device__ __forceinline__ u64 ffma2v(u64 a, u64 b, u64 c){
    u64 d; asm("fma.rn.f32x2 %0, %1, %2, %3;" : "=l"(d) : "l"(a), "l"(b), "l"(c)); return d;
}
__device__ __forceinline__ u64 fadd2(u64 a, u64 b){
    u64 r; asm("add.rn.f32x2 %0, %1, %2;" : "=l"(r) : "l"(a), "l"(b)); return r;
}
__device__ __forceinline__ u64 fmul2(u64 a, u64 b){
    u64 r; asm("mul.rn.f32x2 %0, %1, %2;" : "=l"(r) : "l"(a), "l"(b)); return r;
}

// ---------------- K0: transpose centers, c2 (+bias), zero counters -------------
__global__ void k_prep(const float* __restrict__ ctrs){
    int bid = blockIdx.x, tid = threadIdx.x;
    if(bid < 128){
        int e = bid*256 + tid;           // 32768 elements
        int k = e >> 9, c = e & 511;
        g_ctrT[k*NC + c] = ctrs[c*DIN + k];
    } else {
        int c = (bid-128)*256 + tid;     // 512 centers over 2 blocks
        g_cnt[c] = 0;
        if(c == 0){ g_work = 0; g_flag = 0; }
        const float4* c4 = (const float4*)ctrs;
        float s = 1024.0f;  // bias keeps keys > 0; cancels in softmax
        #pragma unroll
        for(int seg=0; seg<16; seg++){
            float4 v = c4[c*16 + seg];
            s += v.x*v.x + v.y*v.y + v.z*v.z + v.w*v.w;
        }
        g_c2[c] = s;
    }
}

// ---------------- K1: fused distance GEMM + top-16 + softmax + counts ----------
// block: 32 tokens x 512 centers.  256 thr = 8 warps; warp w owns 64 centers.
// lane: og = lane&7 (8 ctr groups of 8), tg = lane>>3 (tokens tg+4i, i<8).
__global__ __launch_bounds__(256) void k_fused(const float* __restrict__ x){
    extern __shared__ char smraw[];
    float* xs  = (float*)smraw;            // 32*64   swizzled x tile
    float* cs  = xs + 32*64;               // 64*512  k-major centers
    float* ds  = cs + 64*512;              // 32*512  distance keys
    float* sdf = ds + 32*512;              // 8*16    selected keys
    int*   sci = (int*)(sdf + 8*16);       // 8*16    selected centers

    int tid = threadIdx.x;
    int ttile = blockIdx.x*32;

    // load x tile (32 tokens), swizzled xs[r*64 + (k ^ 8*(r&3))]
    const float4* x4 = (const float4*)x;
    #pragma unroll
    for(int it=0; it<2; it++){
        int idx2 = tid + 256*it;
        int rr = idx2 >> 4, seg = idx2 & 15;
        float4 v = x4[(ttile+rr)*16 + seg];
        *(float4*)&xs[rr*64 + ((seg*4) ^ ((rr&3)*8))] = v;
    }
    // copy all centers k-major (g_ctrT layout matches cs layout)
    {
        const float4* t4 = (const float4*)g_ctrT;
        float4* cs4 = (float4*)cs;
        #pragma unroll
        for(int f=0; f<32; f++) cs4[tid + 256*f] = t4[tid + 256*f];
    }
    __syncthreads();

    int w  = tid >> 5, lane = tid & 31;
    int og = lane & 7, tg = lane >> 3;     // tg in 0..3
    int cw = w*64;
    int xsw = tg*8;                        // (tg+4i)&3 == tg

    u64 acc[8][4];
    #pragma unroll
    for(int i=0;i<8;i++){ acc[i][0]=0; acc[i][1]=0; acc[i][2]=0; acc[i][3]=0; }

    #pragma unroll 8
    for(int k=0;k<64;k++){
        ulonglong2 p0 = *(const ulonglong2*)&cs[k*NC + cw + og*8];
        ulonglong2 p1 = *(const ulonglong2*)&cs[k*NC + cw + og*8 + 4];
        u64 w0=p0.x, w1=p0.y, w2=p1.x, w3=p1.y;
        int kx = k ^ xsw;
        #pragma unroll
        for(int i=0;i<8;i++){
            u64 xv = dupf(xs[(tg + 4*i)*64 + kx]);
            ffma2(acc[i][0], xv, w0);
            ffma2(acc[i][1], xv, w1);
            ffma2(acc[i][2], xv, w2);
            ffma2(acc[i][3], xv, w3);
        }
    }
    // key = c2b - 2*(x.c), write to ds
    {
        ulonglong2 q0 = *(const ulonglong2*)&g_c2[cw + og*8];
        ulonglong2 q1 = *(const ulonglong2*)&g_c2[cw + og*8 + 4];
        u64 cw0=q0.x, cw1=q0.y, cw2=q1.x, cw3=q1.y;
        u64 m2 = dupf(-2.0f);
        #pragma unroll
        for(int i=0;i<8;i++){
            int r = tg + 4*i;
            ulonglong2* dst = (ulonglong2*)&ds[r*NC + cw + og*8];
            dst[0] = make_ulonglong2(ffma2v(acc[i][0], m2, cw0),
                                     ffma2v(acc[i][1], m2, cw1));
            dst[1] = make_ulonglong2(ffma2v(acc[i][2], m2, cw2),
                                     ffma2v(acc[i][3], m2, cw3));
        }
    }
    __syncthreads();

    // top-16 per token: warp w handles tokens w*4 .. w*4+3
    float* sd  = sdf + w*16;
    int*   sc  = sci + w*16;
    for(int tt=0; tt<4; tt++){
        int t = w*4 + tt;
        const float4* r4 = (const float4*)&ds[t*NC + lane*16];
        float v[16];
        float4 a0=r4[0], a1=r4[1], a2=r4[2], a3=r4[3];
        v[0]=a0.x; v[1]=a0.y; v[2]=a0.z; v[3]=a0.w;
        v[4]=a1.x; v[5]=a1.y; v[6]=a1.z; v[7]=a1.w;
        v[8]=a2.x; v[9]=a2.y; v[10]=a2.z; v[11]=a2.w;
        v[12]=a3.x; v[13]=a3.y; v[14]=a3.z; v[15]=a3.w;

        float lmin = v[0]; int larg = 0;
        #pragma unroll
        for(int i=1;i<16;i++){ if(v[i] < lmin){ lmin=v[i]; larg=i; } }

        #pragma unroll 1
        for(int j=0;j<16;j++){
            // keys > 0 so float bits order-preserve as unsigned
            unsigned mb   = __reduce_min_sync(0xffffffffu, __float_as_uint(lmin));
            unsigned ball = __ballot_sync(0xffffffffu, __float_as_uint(lmin) == mb);
            int wlan = __ffs(ball) - 1;
            if(lane == wlan){
                sd[j] = lmin;
                sc[j] = lane*16 + larg;
                v[larg] = 3.0e38f;
                lmin = v[0]; larg = 0;
                #pragma unroll
                for(int i=1;i<16;i++){ if(v[i] < lmin){ lmin=v[i]; larg=i; } }
            }
            __syncwarp();
        }
        if(lane < 16){
            float d = sd[lane];
            float m = sd[0];
            float e = expf(m - d);
            float s = e;
            #pragma unroll
            for(int o=8;o>=1;o>>=1) s += __shfl_xor_sync(0x0000ffffu, s, o);
            float scv = e / s;
            int c = sc[lane];
            int gt = ttile + t;
            g_scores[gt*16 + lane] = scv;
            g_idx[gt*16 + lane]    = c;
            atomicAdd(&g_cnt[c], 1);
        }
        __syncwarp();
    }
}

// ---------------- K2: fused scan (block 0) + scatter (all 512 blocks) ----------
// 512 blocks x 512 thr: all resident in one wave (592 slots), so the spin on
// g_flag cannot deadlock.
__global__ __launch_bounds__(512) void k_ss(){
    __shared__ int wsum[16];
    int tid = threadIdx.x;

    if(blockIdx.x == 0){
        int c = tid, lane = c & 31, w = c >> 5;
        int cn = g_cnt[c];
        int s = cn;
        #pragma unroll
        for(int o=1;o<32;o<<=1){ int v=__shfl_up_sync(0xffffffffu,s,o); if(lane>=o) s+=v; }
        if(lane==31) wsum[w] = s;
        __syncthreads();
        if(w==0){
            int t = (lane<16) ? wsum[lane] : 0;
            #pragma unroll
            for(int o=1;o<16;o<<=1){ int v=__shfl_up_sync(0xffffffffu,t,o); if(lane>=o) t+=v; }
            if(lane<16) wsum[lane] = t;
        }
        __syncthreads();
        int inc = s + ((w>0) ? wsum[w-1] : 0);
        g_off[c] = inc - cn;
        g_cursor[c] = inc - cn;

        int t = (cn + 127) >> 7;
        __syncthreads();
        int s2 = t;
        #pragma unroll
        for(int o=1;o<32;o<<=1){ int v=__shfl_up_sync(0xffffffffu,s2,o); if(lane>=o) s2+=v; }
        if(lane==31) wsum[w] = s2;
        __syncthreads();
        if(w==0){
            int tt = (lane<16) ? wsum[lane] : 0;
            #pragma unroll
            for(int o=1;o<16;o<<=1){ int v=__shfl_up_sync(0xffffffffu,tt,o); if(lane>=o) tt+=v; }
            if(lane<16) wsum[lane] = tt;
        }
        __syncthreads();
        int tinc = s2 + ((w>0) ? wsum[w-1] : 0);
        int tb = tinc - t;
        for(int i=0;i<t;i++){
            g_tiles[2*(tb+i)]   = c;
            g_tiles[2*(tb+i)+1] = i << 7;
        }
        if(c == 511) g_ntiles = tinc;
        __threadfence();
        __syncthreads();
        if(tid == 0) *((volatile int*)&g_flag) = 1;
    } else {
        if(tid == 0){ while(*((volatile int*)&g_flag) == 0){ } }
        __syncthreads();
    }

    // scatter: one assignment per thread
    int a = blockIdx.x*512 + tid;          // (token<<4)|j
    int c = g_idx[a];
    float s = g_scores[a];
    int pos = atomicAdd(&g_cursor[c], 1);
    g_tok[pos]   = a >> 4;
    g_ascore[pos]= s;
    g_dslot[pos] = a;
}

// ---------------- K3: grouped GEMM per (center, 128-row tile) ------------------
// part[slot] = score * (x[token] @ Wv[c] + Ov[c]).  Dynamic tile scheduling.
__global__ __launch_bounds__(128) void k_gemm(const float* __restrict__ x,
                                              const float* __restrict__ Wv,
                                              const float* __restrict__ Ov){
    __shared__ float ws[DIN*DOUT];   // ws[k*64 + p] (row-major copy of Wv[c])
    __shared__ float xs[128*DIN];    // swizzled like k_fused
    __shared__ int s_tile;
    int nt = g_ntiles;
    int tid = threadIdx.x;
    int og = tid & 7, tg = tid >> 3;
    int xsw = (tg & 3) * 8;
    const float4* x4 = (const float4*)x;

    while(true){
        __syncthreads();             // smem reuse + s_tile protection
        if(tid == 0) s_tile = atomicAdd(&g_work, 1);
        __syncthreads();
        int tile = s_tile;
        if(tile >= nt) break;

        int c      = g_tiles[2*tile];
        int rstart = g_tiles[2*tile+1];
        int base   = g_off[c] + rstart;
        int m      = g_cnt[c] - rstart; if(m > 128) m = 128;

        const float4* wv4 = (const float4*)(Wv + (size_t)c*4096);
        float4* ws4 = (float4*)ws;
        #pragma unroll
        for(int f=0; f<8; f++) ws4[tid + 128*f] = wv4[tid + 128*f];

        #pragma unroll
        for(int it=0; it<16; it++){
            int idx2 = tid + 128*it;
            int rr = idx2 >> 4, seg = idx2 & 15;
            if(rr < m){
                float4 v = x4[g_tok[base+rr]*16 + seg];
                *(float4*)&xs[rr*64 + ((seg*4) ^ ((rr&3)*8))] = v;
            }
        }
        __syncthreads();

        u64 acc[8][4];
        #pragma unroll
        for(int i=0;i<8;i++){ acc[i][0]=0; acc[i][1]=0; acc[i][2]=0; acc[i][3]=0; }

        #pragma unroll 8
        for(int k=0;k<64;k++){
            ulonglong2 p0 = *(const ulonglong2*)&ws[k*64 + og*8];
            ulonglong2 p1 = *(const ulonglong2*)&ws[k*64 + og*8 + 4];
            u64 w0=p0.x, w1=p0.y, w2=p1.x, w3=p1.y;
            int kx = k ^ xsw;
            #pragma unroll
            for(int i=0;i<8;i++){
                u64 xv = dupf(xs[(tg + 16*i)*64 + kx]);
                ffma2(acc[i][0], xv, w0);
                ffma2(acc[i][1], xv, w1);
                ffma2(acc[i][2], xv, w2);
                ffma2(acc[i][3], xv, w3);
            }
        }
        ulonglong2 q0 = *(const ulonglong2*)&Ov[(size_t)c*64 + og*8];
        ulonglong2 q1 = *(const ulonglong2*)&Ov[(size_t)c*64 + og*8 + 4];
        u64 ov0=q0.x, ov1=q0.y, ov2=q1.x, ov3=q1.y;
        #pragma unroll
        for(int i=0;i<8;i++){
            int r = tg + 16*i;
            if(r < m){
                int slot = g_dslot[base + r];
                u64 sv = dupf(g_ascore[base + r]);
                ulonglong2* dst = (ulonglong2*)&g_part[(size_t)slot*64 + og*8];
                dst[0] = make_ulonglong2(fmul2(fadd2(acc[i][0], ov0), sv),
                                         fmul2(fadd2(acc[i][1], ov1), sv));
                dst[1] = make_ulonglong2(fmul2(fadd2(acc[i][2], ov2), sv),
                                         fmul2(fadd2(acc[i][3], ov3), sv));
            }
        }
    }
}

// ---------------- K4: streamed reduce of 16 contiguous partials per token ------
__global__ __launch_bounds__(256) void k_reduce(float* __restrict__ out){
    int t  = blockIdx.x*16 + (threadIdx.x >> 4);
    int c4 = threadIdx.x & 15;
    const float4* p = (const float4*)(g_part + (size_t)t*16*64) + c4;
    float4 acc = make_float4(0.f,0.f,0.f,0.f);
    #pragma unroll
    for(int j=0;j<16;j++){
        float4 v = p[j*16];
        acc.x += v.x; acc.y += v.y; acc.z += v.z; acc.w += v.w;
    }
    ((float4*)out)[t*16 + c4] = acc;
}

// ---------------- launch -------------------------------------------------------
extern "C" void kernel_launch(void* const* d_in, const int* in_sizes, int n_in,
                              void* d_out, int out_size){
    const float* x    = (const float*)d_in[0];
    const float* ctrs = (const float*)d_in[1];
    const float* Wv   = (const float*)d_in[2];
    const float* Ov   = (const float*)d_in[3];
    float* out = (float*)d_out;

    const int FUSED_SMEM = (32*64 + 64*512 + 32*512 + 8*16)*4 + 8*16*4;
    cudaFuncSetAttribute(k_fused, cudaFuncAttributeMaxDynamicSharedMemorySize,
                         FUSED_SMEM);

    k_prep  <<<130, 256>>>(ctrs);
    k_fused <<<512, 256, FUSED_SMEM>>>(x);
    k_ss    <<<512, 512>>>();
    k_gemm  <<<592, 128>>>(x, Wv, Ov);
    k_reduce<<<1024, 256>>>(out);
}

// round 4
// speedup vs baseline: 1.2561x; 1.1324x over previous
#include <cuda_runtime.h>
#include <cstdint>

#define NTOK 16384
#define DIN 64
#define DOUT 64
#define NC 512
#define KSEL 16
#define NASSIGN (NTOK*KSEL)

typedef unsigned long long u64;

// ---------------- scratch (device globals: no allocation allowed) -------------
__device__ float g_ctrT[DIN*NC];        // centers transposed [k][c]
__device__ float g_scores[NASSIGN];     // softmax scores per (token, j)
__device__ int   g_idx[NASSIGN];        // selected center per (token, j)
__device__ int   g_cnt[NC];
__device__ int   g_off[NC];
__device__ int   g_cursor[NC];
__device__ int   g_tok[NASSIGN];        // bucket -> token id
__device__ float g_ascore[NASSIGN];     // bucket -> score
__device__ int   g_dslot[NASSIGN];      // bucket -> (token*16+j) destination slot
__device__ float g_part[(size_t)NASSIGN*DOUT]; // 67 MB partials, slot-addressed
__device__ float g_c2[NC];              // ||c||^2 + 1024 bias
__device__ int   g_tiles[8192];         // (center, rowStart) pairs
__device__ int   g_ntiles;
__device__ int   g_work;                // dynamic tile cursor for k_gemm
__device__ int   g_flag;                // scan-done flag for k_ss

// ---------------- packed f32x2 helpers ----------------------------------------
__device__ __forceinline__ u64 dupf(float x){
    u64 r; asm("mov.b64 %0, {%1, %1};" : "=l"(r) : "f"(x)); return r;
}
__device__ __forceinline__ void ffma2(u64 &d, u64 a, u64 b){
    asm("fma.rn.f32x2 %0, %1, %2, %0;" : "+l"(d) : "l"(a), "l"(b));
}
__device__ __forceinline__ u64 ffma2v(u64 a, u64 b, u64 c){
    u64 d; asm("fma.rn.f32x2 %0, %1, %2, %3;" : "=l"(d) : "l"(a), "l"(b), "l"(c)); return d;
}
__device__ __forceinline__ u64 fadd2(u64 a, u64 b){
    u64 r; asm("add.rn.f32x2 %0, %1, %2;" : "=l"(r) : "l"(a), "l"(b)); return r;
}
__device__ __forceinline__ u64 fmul2(u64 a, u64 b){
    u64 r; asm("mul.rn.f32x2 %0, %1, %2;" : "=l"(r) : "l"(a), "l"(b)); return r;
}

// ---------------- K0: transpose centers, c2 (+bias), zero counters -------------
__global__ void k_prep(const float* __restrict__ ctrs){
    int bid = blockIdx.x, tid = threadIdx.x;
    if(bid < 128){
        int e = bid*256 + tid;           // 32768 elements
        int k = e >> 9, c = e & 511;
        g_ctrT[k*NC + c] = ctrs[c*DIN + k];
    } else {
        int c = (bid-128)*256 + tid;     // 512 centers over 2 blocks
        g_cnt[c] = 0;
        if(c == 0){ g_work = 0; g_flag = 0; }
        const float4* c4 = (const float4*)ctrs;
        float s = 1024.0f;  // bias keeps keys > 0; cancels in softmax
        #pragma unroll
        for(int seg=0; seg<16; seg++){
            float4 v = c4[c*16 + seg];
            s += v.x*v.x + v.y*v.y + v.z*v.z + v.w*v.w;
        }
        g_c2[c] = s;
    }
}

// ---------------- K1: fused distance GEMM + top-16 + softmax + counts ----------
// block: 32 tokens x 512 centers.  256 thr = 8 warps; warp w owns 64 centers.
// centers read directly from L2-resident g_ctrT (no smem staging -> 2 blk/SM).
__global__ __launch_bounds__(256,2) void k_fused(const float* __restrict__ x){
    extern __shared__ char smraw[];
    float* xs  = (float*)smraw;            // 32*64   swizzled x tile
    float* ds  = xs + 32*64;               // 32*512  distance keys
    float* sdf = ds + 32*512;              // 8*16    selected keys
    int*   sci = (int*)(sdf + 8*16);       // 8*16    selected centers

    int tid = threadIdx.x;
    int ttile = blockIdx.x*32;

    // load x tile (32 tokens), swizzled xs[r*64 + (k ^ 8*(r&3))]
    const float4* x4 = (const float4*)x;
    #pragma unroll
    for(int it=0; it<2; it++){
        int idx2 = tid + 256*it;
        int rr = idx2 >> 4, seg = idx2 & 15;
        float4 v = x4[(ttile+rr)*16 + seg];
        *(float4*)&xs[rr*64 + ((seg*4) ^ ((rr&3)*8))] = v;
    }
    __syncthreads();

    int w  = tid >> 5, lane = tid & 31;
    int og = lane & 7, tg = lane >> 3;     // tg in 0..3
    int cbase = w*64 + og*8;
    int xsw = tg*8;                        // (tg+4i)&3 == tg

    u64 acc[8][4];
    #pragma unroll
    for(int i=0;i<8;i++){ acc[i][0]=0; acc[i][1]=0; acc[i][2]=0; acc[i][3]=0; }

    #pragma unroll 4
    for(int k4=0;k4<16;k4++){
        float v4[8][4];
        #pragma unroll
        for(int i=0;i<8;i++)
            *(float4*)v4[i] = *(const float4*)&xs[(tg+4*i)*64 + ((k4*4) ^ xsw)];
        #pragma unroll
        for(int kk=0;kk<4;kk++){
            int k = k4*4 + kk;
            ulonglong2 p0 = *(const ulonglong2*)&g_ctrT[k*NC + cbase];
            ulonglong2 p1 = *(const ulonglong2*)&g_ctrT[k*NC + cbase + 4];
            #pragma unroll
            for(int i=0;i<8;i++){
                u64 xv = dupf(v4[i][kk]);
                ffma2(acc[i][0], xv, p0.x);
                ffma2(acc[i][1], xv, p0.y);
                ffma2(acc[i][2], xv, p1.x);
                ffma2(acc[i][3], xv, p1.y);
            }
        }
    }
    // key = c2b - 2*(x.c), write to ds
    {
        ulonglong2 q0 = *(const ulonglong2*)&g_c2[cbase];
        ulonglong2 q1 = *(const ulonglong2*)&g_c2[cbase + 4];
        u64 m2 = dupf(-2.0f);
        #pragma unroll
        for(int i=0;i<8;i++){
            int r = tg + 4*i;
            ulonglong2* dst = (ulonglong2*)&ds[r*NC + cbase];
            dst[0] = make_ulonglong2(ffma2v(acc[i][0], m2, q0.x),
                                     ffma2v(acc[i][1], m2, q0.y));
            dst[1] = make_ulonglong2(ffma2v(acc[i][2], m2, q1.x),
                                     ffma2v(acc[i][3], m2, q1.y));
        }
    }
    __syncthreads();

    // top-16 per token: warp w handles tokens w*4..w*4+3.
    // stride-32 scalar reads: conflict-free.
    float* sd  = sdf + w*16;
    int*   sc  = sci + w*16;
    for(int tt=0; tt<4; tt++){
        int t = w*4 + tt;
        float v[16];
        #pragma unroll
        for(int i=0;i<16;i++) v[i] = ds[t*NC + lane + 32*i];

        float lmin = v[0]; int larg = 0;
        #pragma unroll
        for(int i=1;i<16;i++){ if(v[i] < lmin){ lmin=v[i]; larg=i; } }

        #pragma unroll 1
        for(int j=0;j<16;j++){
            // keys > 0 so float bits order-preserve as unsigned
            unsigned mb   = __reduce_min_sync(0xffffffffu, __float_as_uint(lmin));
            unsigned ball = __ballot_sync(0xffffffffu, __float_as_uint(lmin) == mb);
            int wlan = __ffs(ball) - 1;
            if(lane == wlan){
                sd[j] = lmin;
                sc[j] = larg*32 + lane;
                v[larg] = 3.0e38f;
                lmin = v[0]; larg = 0;
                #pragma unroll
                for(int i=1;i<16;i++){ if(v[i] < lmin){ lmin=v[i]; larg=i; } }
            }
            __syncwarp();
        }
        if(lane < 16){
            float d = sd[lane];
            float m = sd[0];
            float e = expf(m - d);
            float s = e;
            #pragma unroll
            for(int o=8;o>=1;o>>=1) s += __shfl_xor_sync(0x0000ffffu, s, o);
            float scv = e / s;
            int c = sc[lane];
            int gt = ttile + t;
            g_scores[gt*16 + lane] = scv;
            g_idx[gt*16 + lane]    = c;
            atomicAdd(&g_cnt[c], 1);
        }
        __syncwarp();
    }
}

// ---------------- K2: fused scan (block 0) + scatter (all 512 blocks) ----------
__global__ __launch_bounds__(512) void k_ss(){
    __shared__ int wsum[16];
    int tid = threadIdx.x;

    if(blockIdx.x == 0){
        int c = tid, lane = c & 31, w = c >> 5;
        int cn = g_cnt[c];
        int s = cn;
        #pragma unroll
        for(int o=1;o<32;o<<=1){ int v=__shfl_up_sync(0xffffffffu,s,o); if(lane>=o) s+=v; }
        if(lane==31) wsum[w] = s;
        __syncthreads();
        if(w==0){
            int t = (lane<16) ? wsum[lane] : 0;
            #pragma unroll
            for(int o=1;o<16;o<<=1){ int v=__shfl_up_sync(0xffffffffu,t,o); if(lane>=o) t+=v; }
            if(lane<16) wsum[lane] = t;
        }
        __syncthreads();
        int inc = s + ((w>0) ? wsum[w-1] : 0);
        g_off[c] = inc - cn;
        g_cursor[c] = inc - cn;

        int t = (cn + 127) >> 7;
        __syncthreads();
        int s2 = t;
        #pragma unroll
        for(int o=1;o<32;o<<=1){ int v=__shfl_up_sync(0xffffffffu,s2,o); if(lane>=o) s2+=v; }
        if(lane==31) wsum[w] = s2;
        __syncthreads();
        if(w==0){
            int tt = (lane<16) ? wsum[lane] : 0;
            #pragma unroll
            for(int o=1;o<16;o<<=1){ int v=__shfl_up_sync(0xffffffffu,tt,o); if(lane>=o) tt+=v; }
            if(lane<16) wsum[lane] = tt;
        }
        __syncthreads();
        int tinc = s2 + ((w>0) ? wsum[w-1] : 0);
        int tb = tinc - t;
        for(int i=0;i<t;i++){
            g_tiles[2*(tb+i)]   = c;
            g_tiles[2*(tb+i)+1] = i << 7;
        }
        if(c == 511) g_ntiles = tinc;
        __threadfence();
        __syncthreads();
        if(tid == 0) *((volatile int*)&g_flag) = 1;
    } else {
        if(tid == 0){ while(*((volatile int*)&g_flag) == 0){ } }
        __syncthreads();
    }

    // scatter: one assignment per thread
    int a = blockIdx.x*512 + tid;          // (token<<4)|j
    int c = g_idx[a];
    float s = g_scores[a];
    int pos = atomicAdd(&g_cursor[c], 1);
    g_tok[pos]   = a >> 4;
    g_ascore[pos]= s;
    g_dslot[pos] = a;
}

// ---------------- K3: grouped GEMM per (center, 128-row tile) ------------------
// part[slot] = score * (x[token] @ Wv[c] + Ov[c]).  Dynamic tile scheduling.
__global__ __launch_bounds__(128,4) void k_gemm(const float* __restrict__ x,
                                                const float* __restrict__ Wv,
                                                const float* __restrict__ Ov){
    __shared__ float ws[DIN*DOUT];   // ws[k*64 + p] (row-major copy of Wv[c])
    __shared__ float xs[128*DIN];    // swizzled like k_fused
    __shared__ int s_tile;
    int nt = g_ntiles;
    int tid = threadIdx.x;
    int og = tid & 7, tg = tid >> 3;
    int xsw = (tg & 3) * 8;
    const float4* x4 = (const float4*)x;

    while(true){
        __syncthreads();             // smem reuse + s_tile protection
        if(tid == 0) s_tile = atomicAdd(&g_work, 1);
        __syncthreads();
        int tile = s_tile;
        if(tile >= nt) break;

        int c      = g_tiles[2*tile];
        int rstart = g_tiles[2*tile+1];
        int base   = g_off[c] + rstart;
        int m      = g_cnt[c] - rstart; if(m > 128) m = 128;

        const float4* wv4 = (const float4*)(Wv + (size_t)c*4096);
        float4* ws4 = (float4*)ws;
        #pragma unroll
        for(int f=0; f<8; f++) ws4[tid + 128*f] = wv4[tid + 128*f];

        #pragma unroll
        for(int it=0; it<16; it++){
            int idx2 = tid + 128*it;
            int rr = idx2 >> 4, seg = idx2 & 15;
            if(rr < m){
                float4 v = x4[g_tok[base+rr]*16 + seg];
                *(float4*)&xs[rr*64 + ((seg*4) ^ ((rr&3)*8))] = v;
            }
        }
        __syncthreads();

        u64 acc[8][4];
        #pragma unroll
        for(int i=0;i<8;i++){ acc[i][0]=0; acc[i][1]=0; acc[i][2]=0; acc[i][3]=0; }

        #pragma unroll 4
        for(int k4=0;k4<16;k4++){
            float v4[8][4];
            #pragma unroll
            for(int i=0;i<8;i++)
                *(float4*)v4[i] = *(const float4*)&xs[(tg+16*i)*64 + ((k4*4) ^ xsw)];
            #pragma unroll
            for(int kk=0;kk<4;kk++){
                int k = k4*4 + kk;
                ulonglong2 p0 = *(const ulonglong2*)&ws[k*64 + og*8];
                ulonglong2 p1 = *(const ulonglong2*)&ws[k*64 + og*8 + 4];
                #pragma unroll
                for(int i=0;i<8;i++){
                    u64 xv = dupf(v4[i][kk]);
                    ffma2(acc[i][0], xv, p0.x);
                    ffma2(acc[i][1], xv, p0.y);
                    ffma2(acc[i][2], xv, p1.x);
                    ffma2(acc[i][3], xv, p1.y);
                }
            }
        }
        ulonglong2 q0 = *(const ulonglong2*)&Ov[(size_t)c*64 + og*8];
        ulonglong2 q1 = *(const ulonglong2*)&Ov[(size_t)c*64 + og*8 + 4];
        #pragma unroll
        for(int i=0;i<8;i++){
            int r = tg + 16*i;
            if(r < m){
                int slot = g_dslot[base + r];
                u64 sv = dupf(g_ascore[base + r]);
                ulonglong2* dst = (ulonglong2*)&g_part[(size_t)slot*64 + og*8];
                dst[0] = make_ulonglong2(fmul2(fadd2(acc[i][0], q0.x), sv),
                                         fmul2(fadd2(acc[i][1], q0.y), sv));
                dst[1] = make_ulonglong2(fmul2(fadd2(acc[i][2], q1.x), sv),
                                         fmul2(fadd2(acc[i][3], q1.y), sv));
            }
        }
    }
}

// ---------------- K4: streamed reduce of 16 contiguous partials per token ------
__global__ __launch_bounds__(256) void k_reduce(float* __restrict__ out){
    int t  = blockIdx.x*16 + (threadIdx.x >> 4);
    int c4 = threadIdx.x & 15;
    const float4* p = (const float4*)(g_part + (size_t)t*16*64) + c4;
    float4 acc = make_float4(0.f,0.f,0.f,0.f);
    #pragma unroll
    for(int j=0;j<16;j++){
        float4 v = p[j*16];
        acc.x += v.x; acc.y += v.y; acc.z += v.z; acc.w += v.w;
    }
    ((float4*)out)[t*16 + c4] = acc;
}

// ---------------- launch -------------------------------------------------------
extern "C" void kernel_launch(void* const* d_in, const int* in_sizes, int n_in,
                              void* d_out, int out_size){
    const float* x    = (const float*)d_in[0];
    const float* ctrs = (const float*)d_in[1];
    const float* Wv   = (const float*)d_in[2];
    const float* Ov   = (const float*)d_in[3];
    float* out = (float*)d_out;

    const int FUSED_SMEM = (32*64 + 32*512 + 8*16)*4 + 8*16*4;
    cudaFuncSetAttribute(k_fused, cudaFuncAttributeMaxDynamicSharedMemorySize,
                         FUSED_SMEM);

    k_prep  <<<130, 256>>>(ctrs);
    k_fused <<<512, 256, FUSED_SMEM>>>(x);
    k_ss    <<<512, 512>>>();
    k_gemm  <<<592, 128>>>(x, Wv, Ov);
    k_reduce<<<1024, 256>>>(out);
}

// round 5
// speedup vs baseline: 1.2958x; 1.0316x over previous
#include <cuda_runtime.h>
#include <cstdint>

#define NTOK 16384
#define DIN 64
#define DOUT 64
#define NC 512
#define KSEL 16
#define NASSIGN (NTOK*KSEL)

typedef unsigned long long u64;

// ---------------- scratch (device globals: no allocation allowed) -------------
__device__ float g_ctrT[DIN*NC];        // centers transposed [k][c]
__device__ float g_scores[NASSIGN];     // softmax scores per (token, j)
__device__ int   g_idx[NASSIGN];        // selected center per (token, j)
__device__ int   g_cnt[NC];
__device__ int   g_off[NC];
__device__ int   g_cursor[NC];
__device__ int   g_tok[NASSIGN];        // bucket -> token id
__device__ float g_ascore[NASSIGN];     // bucket -> score
__device__ int   g_dslot[NASSIGN];      // bucket -> (token*16+j) destination slot
__device__ float g_part[(size_t)NASSIGN*DOUT]; // 67 MB partials, slot-addressed
__device__ float g_c2[NC];              // ||c||^2 + 1024 bias
__device__ int   g_tiles[8192];         // (center, rowStart) pairs
__device__ int   g_ntiles;
__device__ int   g_work;                // dynamic tile cursor for k_gemm
__device__ int   g_flag;                // scan-done flag for k_ss

// ---------------- packed f32x2 helpers ----------------------------------------
__device__ __forceinline__ u64 dupf(float x){
    u64 r; asm("mov.b64 %0, {%1, %1};" : "=l"(r) : "f"(x)); return r;
}
__device__ __forceinline__ void ffma2(u64 &d, u64 a, u64 b){
    asm("fma.rn.f32x2 %0, %1, %2, %0;" : "+l"(d) : "l"(a), "l"(b));
}
__device__ __forceinline__ u64 ffma2v(u64 a, u64 b, u64 c){
    u64 d; asm("fma.rn.f32x2 %0, %1, %2, %3;" : "=l"(d) : "l"(a), "l"(b), "l"(c)); return d;
}
__device__ __forceinline__ u64 fadd2(u64 a, u64 b){
    u64 r; asm("add.rn.f32x2 %0, %1, %2;" : "=l"(r) : "l"(a), "l"(b)); return r;
}
__device__ __forceinline__ u64 fmul2(u64 a, u64 b){
    u64 r; asm("mul.rn.f32x2 %0, %1, %2;" : "=l"(r) : "l"(a), "l"(b)); return r;
}

// ---------------- K0: transpose centers, c2 (+bias), zero counters -------------
__global__ void k_prep(const float* __restrict__ ctrs){
    int bid = blockIdx.x, tid = threadIdx.x;
    if(bid < 128){
        int e = bid*256 + tid;           // 32768 elements
        int k = e >> 9, c = e & 511;
        g_ctrT[k*NC + c] = ctrs[c*DIN + k];
    } else {
        int c = (bid-128)*256 + tid;     // 512 centers over 2 blocks
        g_cnt[c] = 0;
        if(c == 0){ g_work = 0; g_flag = 0; }
        const float4* c4 = (const float4*)ctrs;
        float s = 1024.0f;  // bias keeps keys > 0; cancels in softmax
        #pragma unroll
        for(int seg=0; seg<16; seg++){
            float4 v = c4[c*16 + seg];
            s += v.x*v.x + v.y*v.y + v.z*v.z + v.w*v.w;
        }
        g_c2[c] = s;
    }
}

// ---------------- K1: fused distance GEMM + top-16 + softmax + counts ----------
__global__ __launch_bounds__(256,2) void k_fused(const float* __restrict__ x){
    extern __shared__ char smraw[];
    float* xs  = (float*)smraw;            // 32*64   swizzled x tile
    float* ds  = xs + 32*64;               // 32*512  distance keys
    float* sdf = ds + 32*512;              // 8*16    selected keys
    int*   sci = (int*)(sdf + 8*16);       // 8*16    selected centers

    int tid = threadIdx.x;
    int ttile = blockIdx.x*32;

    const float4* x4 = (const float4*)x;
    #pragma unroll
    for(int it=0; it<2; it++){
        int idx2 = tid + 256*it;
        int rr = idx2 >> 4, seg = idx2 & 15;
        float4 v = x4[(ttile+rr)*16 + seg];
        *(float4*)&xs[rr*64 + ((seg*4) ^ ((rr&3)*8))] = v;
    }
    __syncthreads();

    int w  = tid >> 5, lane = tid & 31;
    int og = lane & 7, tg = lane >> 3;     // tg in 0..3
    int cbase = w*64 + og*8;
    int xsw = tg*8;

    u64 acc[8][4];
    #pragma unroll
    for(int i=0;i<8;i++){ acc[i][0]=0; acc[i][1]=0; acc[i][2]=0; acc[i][3]=0; }

    #pragma unroll 4
    for(int k4=0;k4<16;k4++){
        float v4[8][4];
        #pragma unroll
        for(int i=0;i<8;i++)
            *(float4*)v4[i] = *(const float4*)&xs[(tg+4*i)*64 + ((k4*4) ^ xsw)];
        #pragma unroll
        for(int kk=0;kk<4;kk++){
            int k = k4*4 + kk;
            ulonglong2 p0 = *(const ulonglong2*)&g_ctrT[k*NC + cbase];
            ulonglong2 p1 = *(const ulonglong2*)&g_ctrT[k*NC + cbase + 4];
            #pragma unroll
            for(int i=0;i<8;i++){
                u64 xv = dupf(v4[i][kk]);
                ffma2(acc[i][0], xv, p0.x);
                ffma2(acc[i][1], xv, p0.y);
                ffma2(acc[i][2], xv, p1.x);
                ffma2(acc[i][3], xv, p1.y);
            }
        }
    }
    {
        ulonglong2 q0 = *(const ulonglong2*)&g_c2[cbase];
        ulonglong2 q1 = *(const ulonglong2*)&g_c2[cbase + 4];
        u64 m2 = dupf(-2.0f);
        #pragma unroll
        for(int i=0;i<8;i++){
            int r = tg + 4*i;
            ulonglong2* dst = (ulonglong2*)&ds[r*NC + cbase];
            dst[0] = make_ulonglong2(ffma2v(acc[i][0], m2, q0.x),
                                     ffma2v(acc[i][1], m2, q0.y));
            dst[1] = make_ulonglong2(ffma2v(acc[i][2], m2, q1.x),
                                     ffma2v(acc[i][3], m2, q1.y));
        }
    }
    __syncthreads();

    float* sd  = sdf + w*16;
    int*   sc  = sci + w*16;
    for(int tt=0; tt<4; tt++){
        int t = w*4 + tt;
        float v[16];
        #pragma unroll
        for(int i=0;i<16;i++) v[i] = ds[t*NC + lane + 32*i];

        float lmin = v[0]; int larg = 0;
        #pragma unroll
        for(int i=1;i<16;i++){ if(v[i] < lmin){ lmin=v[i]; larg=i; } }

        #pragma unroll 1
        for(int j=0;j<16;j++){
            unsigned mb   = __reduce_min_sync(0xffffffffu, __float_as_uint(lmin));
            unsigned ball = __ballot_sync(0xffffffffu, __float_as_uint(lmin) == mb);
            int wlan = __ffs(ball) - 1;
            if(lane == wlan){
                sd[j] = lmin;
                sc[j] = larg*32 + lane;
                v[larg] = 3.0e38f;
                lmin = v[0]; larg = 0;
                #pragma unroll
                for(int i=1;i<16;i++){ if(v[i] < lmin){ lmin=v[i]; larg=i; } }
            }
            __syncwarp();
        }
        if(lane < 16){
            float d = sd[lane];
            float m = sd[0];
            float e = expf(m - d);
            float s = e;
            #pragma unroll
            for(int o=8;o>=1;o>>=1) s += __shfl_xor_sync(0x0000ffffu, s, o);
            float scv = e / s;
            int c = sc[lane];
            int gt = ttile + t;
            g_scores[gt*16 + lane] = scv;
            g_idx[gt*16 + lane]    = c;
            atomicAdd(&g_cnt[c], 1);
        }
        __syncwarp();
    }
}

// ---------------- K2: fused scan (block 0) + scatter (all 512 blocks) ----------
__global__ __launch_bounds__(512) void k_ss(){
    __shared__ int wsum[16];
    int tid = threadIdx.x;

    if(blockIdx.x == 0){
        int c = tid, lane = c & 31, w = c >> 5;
        int cn = g_cnt[c];
        int s = cn;
        #pragma unroll
        for(int o=1;o<32;o<<=1){ int v=__shfl_up_sync(0xffffffffu,s,o); if(lane>=o) s+=v; }
        if(lane==31) wsum[w] = s;
        __syncthreads();
        if(w==0){
            int t = (lane<16) ? wsum[lane] : 0;
            #pragma unroll
            for(int o=1;o<16;o<<=1){ int v=__shfl_up_sync(0xffffffffu,t,o); if(lane>=o) t+=v; }
            if(lane<16) wsum[lane] = t;
        }
        __syncthreads();
        int inc = s + ((w>0) ? wsum[w-1] : 0);
        g_off[c] = inc - cn;
        g_cursor[c] = inc - cn;

        int t = (cn + 127) >> 7;
        __syncthreads();
        int s2 = t;
        #pragma unroll
        for(int o=1;o<32;o<<=1){ int v=__shfl_up_sync(0xffffffffu,s2,o); if(lane>=o) s2+=v; }
        if(lane==31) wsum[w] = s2;
        __syncthreads();
        if(w==0){
            int tt = (lane<16) ? wsum[lane] : 0;
            #pragma unroll
            for(int o=1;o<16;o<<=1){ int v=__shfl_up_sync(0xffffffffu,tt,o); if(lane>=o) tt+=v; }
            if(lane<16) wsum[lane] = tt;
        }
        __syncthreads();
        int tinc = s2 + ((w>0) ? wsum[w-1] : 0);
        int tb = tinc - t;
        for(int i=0;i<t;i++){
            g_tiles[2*(tb+i)]   = c;
            g_tiles[2*(tb+i)+1] = i << 7;
        }
        if(c == 511) g_ntiles = tinc;
        __threadfence();
        __syncthreads();
        if(tid == 0) *((volatile int*)&g_flag) = 1;
    } else {
        if(tid == 0){ while(*((volatile int*)&g_flag) == 0){ } }
        __syncthreads();
    }

    int a = blockIdx.x*512 + tid;          // (token<<4)|j
    int c = g_idx[a];
    float s = g_scores[a];
    int pos = atomicAdd(&g_cursor[c], 1);
    g_tok[pos]   = a >> 4;
    g_ascore[pos]= s;
    g_dslot[pos] = a;
}

// ---------------- K3: grouped GEMM per (center, 128-row tile) ------------------
// 256 thr, thread tile 4 rows (contiguous) x 8 cols (split og*4 / og*4+32).
// Warp w owns rows [16w, 16w+16): whole-warp skip when 16w >= m kills padding.
__global__ __launch_bounds__(256,3) void k_gemm(const float* __restrict__ x,
                                                const float* __restrict__ Wv,
                                                const float* __restrict__ Ov){
    __shared__ float ws[DIN*DOUT];   // ws[k*64 + p] (row-major copy of Wv[c])
    __shared__ float xs[128*DIN];    // xs[r*64 + (k ^ 8*((r>>2)&3))]
    __shared__ int s_tile;
    int nt = g_ntiles;
    int tid = threadIdx.x;
    int og = tid & 7, tg = tid >> 3;     // tg 0..31
    int w  = tid >> 5;
    int xsw = (tg & 3) * 8;              // rows tg*4..tg*4+3 share (r>>2)&3 == tg&3
    const float4* x4 = (const float4*)x;

    while(true){
        __syncthreads();             // smem reuse + s_tile protection
        if(tid == 0) s_tile = atomicAdd(&g_work, 1);
        __syncthreads();
        int tile = s_tile;
        if(tile >= nt) break;

        int c      = g_tiles[2*tile];
        int rstart = g_tiles[2*tile+1];
        int base   = g_off[c] + rstart;
        int m      = g_cnt[c] - rstart; if(m > 128) m = 128;

        const float4* wv4 = (const float4*)(Wv + (size_t)c*4096);
        float4* ws4 = (float4*)ws;
        #pragma unroll
        for(int f=0; f<4; f++) ws4[tid + 256*f] = wv4[tid + 256*f];

        #pragma unroll
        for(int it=0; it<8; it++){
            int idx2 = tid + 256*it;
            int rr = idx2 >> 4, seg = idx2 & 15;
            if(rr < m){
                float4 v = x4[g_tok[base+rr]*16 + seg];
                *(float4*)&xs[rr*64 + ((seg*4) ^ (((rr>>2)&3)*8))] = v;
            }
        }
        __syncthreads();

        if(16*w < m){                   // warp-uniform: skip padded rows
            u64 acc[4][4];
            #pragma unroll
            for(int i=0;i<4;i++){ acc[i][0]=0; acc[i][1]=0; acc[i][2]=0; acc[i][3]=0; }

            #pragma unroll 4
            for(int k4=0;k4<16;k4++){
                float v4[4][4];
                #pragma unroll
                for(int i=0;i<4;i++)
                    *(float4*)v4[i] = *(const float4*)&xs[(tg*4+i)*64 + ((k4*4) ^ xsw)];
                #pragma unroll
                for(int kk=0;kk<4;kk++){
                    int k = k4*4 + kk;
                    ulonglong2 p0 = *(const ulonglong2*)&ws[k*64 + og*4];
                    ulonglong2 p1 = *(const ulonglong2*)&ws[k*64 + og*4 + 32];
                    #pragma unroll
                    for(int i=0;i<4;i++){
                        u64 xv = dupf(v4[i][kk]);
                        ffma2(acc[i][0], xv, p0.x);
                        ffma2(acc[i][1], xv, p0.y);
                        ffma2(acc[i][2], xv, p1.x);
                        ffma2(acc[i][3], xv, p1.y);
                    }
                }
            }
            ulonglong2 q0 = *(const ulonglong2*)&Ov[(size_t)c*64 + og*4];
            ulonglong2 q1 = *(const ulonglong2*)&Ov[(size_t)c*64 + og*4 + 32];
            #pragma unroll
            for(int i=0;i<4;i++){
                int r = tg*4 + i;
                if(r < m){
                    int slot = g_dslot[base + r];
                    u64 sv = dupf(g_ascore[base + r]);
                    ulonglong2* d0 = (ulonglong2*)&g_part[(size_t)slot*64 + og*4];
                    ulonglong2* d1 = (ulonglong2*)&g_part[(size_t)slot*64 + og*4 + 32];
                    *d0 = make_ulonglong2(fmul2(fadd2(acc[i][0], q0.x), sv),
                                          fmul2(fadd2(acc[i][1], q0.y), sv));
                    *d1 = make_ulonglong2(fmul2(fadd2(acc[i][2], q1.x), sv),
                                          fmul2(fadd2(acc[i][3], q1.y), sv));
                }
            }
        }
    }
}

// ---------------- K4: streamed reduce of 16 contiguous partials per token ------
__global__ __launch_bounds__(256) void k_reduce(float* __restrict__ out){
    int t  = blockIdx.x*16 + (threadIdx.x >> 4);
    int c4 = threadIdx.x & 15;
    const float4* p = (const float4*)(g_part + (size_t)t*16*64) + c4;
    float4 acc = make_float4(0.f,0.f,0.f,0.f);
    #pragma unroll
    for(int j=0;j<16;j++){
        float4 v = p[j*16];
        acc.x += v.x; acc.y += v.y; acc.z += v.z; acc.w += v.w;
    }
    ((float4*)out)[t*16 + c4] = acc;
}

// ---------------- launch -------------------------------------------------------
extern "C" void kernel_launch(void* const* d_in, const int* in_sizes, int n_in,
                              void* d_out, int out_size){
    const float* x    = (const float*)d_in[0];
    const float* ctrs = (const float*)d_in[1];
    const float* Wv   = (const float*)d_in[2];
    const float* Ov   = (const float*)d_in[3];
    float* out = (float*)d_out;

    const int FUSED_SMEM = (32*64 + 32*512 + 8*16)*4 + 8*16*4;
    cudaFuncSetAttribute(k_fused, cudaFuncAttributeMaxDynamicSharedMemorySize,
                         FUSED_SMEM);

    k_prep  <<<130, 256>>>(ctrs);
    k_fused <<<512, 256, FUSED_SMEM>>>(x);
    k_ss    <<<512, 512>>>();
    k_gemm  <<<444, 256>>>(x, Wv, Ov);
    k_reduce<<<1024, 256>>>(out);
}